// round 10
// baseline (speedup 1.0000x reference)
#include <cuda_runtime.h>
#include <cuda_bf16.h>
#include <cstdint>

// Output = one_hot(arange(N), N) @ W = I @ W = W: an 8 MiB D2D copy.
//
// Converged result of an 8-round sweep (LDG geometries MLP1/4/8 at grids
// 256-2048, cache ops default/.cg/.cs, TMA bulk copy, CE memcpy, and a
// concurrent SM+CE split): every variant lands in a 5.89-6.43us kernel /
// 6.6-7.2us wallclock band with all ncu counters <=18%. The limiter is
// environmental, not architectural: a ~6us burst graph never ramps DVFS,
// so each replay pays launch + one idle-clock memory round-trip + ~1.8us
// of transfer at the down-clocked fabric rate. Traffic (8 MiB read +
// 8 MiB write through L2) is the information-theoretic minimum.
//
// This kernel is the empirically-best configuration from the sweep
// (session-minimum 5.888us kernel / 6.592us wallclock): plain LDG.128,
// 512 CTAs x 256 threads x 4 vec4, front-batched loads, exact tiling,
// no cache hints (hints measured mildly negative: .cg +0.16us,
// .cg+.cs +0.32us kernel time).

__global__ void __launch_bounds__(256) copy_w_mlp4(const float4* __restrict__ src,
                                                   float4* __restrict__ dst) {
    // Each CTA owns a contiguous 16 KiB tile (1024 vec4); thread t handles
    // {base+t, base+t+256, base+t+512, base+t+768} -> every warp access is
    // one fully-coalesced 128B line. 4 independent loads issue back-to-back
    // (MLP_p1 = 4) before any store; no loops, branches, or bounds checks
    // (524288 vec4 = 512 * 256 * 4 exactly; N=16384, D=128 are static).
    int base = blockIdx.x * (256 * 4) + threadIdx.x;

    float4 a0 = src[base + 0 * 256];
    float4 a1 = src[base + 1 * 256];
    float4 a2 = src[base + 2 * 256];
    float4 a3 = src[base + 3 * 256];

    dst[base + 0 * 256] = a0;
    dst[base + 1 * 256] = a1;
    dst[base + 2 * 256] = a2;
    dst[base + 3 * 256] = a3;
}

extern "C" void kernel_launch(void* const* d_in, const int* in_sizes, int n_in,
                              void* d_out, int out_size) {
    const float4* W = (const float4*)d_in[0];
    float4* out = (float4*)d_out;
    // out_size = 16384*128 = 2097152 floats = 524288 vec4 -> 512 CTAs exact.
    int blocks = out_size / (4 * 256 * 4);
    copy_w_mlp4<<<blocks, 256>>>(W, out);
}

// round 14
// speedup vs baseline: 1.0047x; 1.0047x over previous
#include <cuda_runtime.h>
#include <cuda_bf16.h>
#include <cstdint>

// Output = one_hot(arange(N), N) @ W = I @ W = W: an 8 MiB D2D copy.
//
// Session model (R1-R10): wallclock = ~6.0us kernel floor (idle-DVFS
// launch + one memory round-trip + the mandatory 16 MiB of L2 traffic)
// + 0.5-0.9us graph-replay overhead; run-to-run noise +-0.3us. Invariant
// across LDG geometry, cache ops, TMA bulk, CE memcpy, and dual-engine
// split. Last untested mechanism: sm_10x 256-bit global accesses
// (LDG.E.256/STG.E.256) -- half the instructions and half the per-warp
// L1tex queue entries at identical traffic. Winning tiling kept:
// 512 CTAs x 256 threads, contiguous 16 KiB per CTA, loads front-batched,
// exact fit (512*256*2 x 32B = 8 MiB), no loops or bounds checks.

struct alignas(32) vec32 { float4 lo, hi; };  // 32-byte aligned -> LDG.E.256 on sm_103a

__global__ void __launch_bounds__(256) copy_w_v256(const vec32* __restrict__ src,
                                                   vec32* __restrict__ dst) {
    // 262144 vec32 total; CTA tile = 512 vec32 (16 KiB); thread t handles
    // {base+t, base+t+256}: each warp access is a contiguous 1 KiB span
    // (2 x 128B lines per thread-quad), fully coalesced.
    int base = blockIdx.x * (256 * 2) + threadIdx.x;

    vec32 a0 = src[base + 0 * 256];
    vec32 a1 = src[base + 1 * 256];

    dst[base + 0 * 256] = a0;
    dst[base + 1 * 256] = a1;
}

extern "C" void kernel_launch(void* const* d_in, const int* in_sizes, int n_in,
                              void* d_out, int out_size) {
    const vec32* W = (const vec32*)d_in[0];
    vec32* out = (vec32*)d_out;
    // out_size = 2097152 floats = 262144 vec32 -> 512 CTAs exact.
    int blocks = out_size / (8 * 256 * 2);
    copy_w_v256<<<blocks, 256>>>(W, out);
}

// round 15
// speedup vs baseline: 1.0435x; 1.0386x over previous
#include <cuda_runtime.h>
#include <cuda_bf16.h>
#include <cstdint>

// Output = one_hot(arange(N), N) @ W = I @ W = W: an 8 MiB D2D copy.
//
// FINAL kernel — converged result of a 14-round sweep on GB300:
//   tested: LDG geometries (MLP1/4/8, grids 256-2048), LDG.128 vs
//   LDG.E.256, cache ops (default/.cg/.cs), TMA bulk copy (UBLKCP,
//   double-buffered), CE memcpy graph node, and a concurrent SM+CE
//   dual-engine split.
//   result: kernel 5.89-6.43us / wallclock 6.59-7.20us for ALL variants,
//   every ncu counter <=18%, run-to-run noise +-0.3us.
// The limiter is environmental: a ~6us burst graph never ramps DVFS, so
// each replay pays launch + one idle-clock memory round-trip + the
// mandatory 16 MiB of L2 traffic (8 read + 8 write — the information-
// theoretic minimum, since out must byte-equal W) at the down-clocked
// fabric rate, plus ~0.5-0.9us graph-replay overhead.
//
// This is the best-measured configuration (session minima: 5.888us
// kernel, 6.592us wallclock): plain LDG.128/STG.128, 512 CTAs x 256
// threads x 4 vec4, contiguous 16 KiB tile per CTA, 4 independent loads
// front-batched before any store, exact tiling, no hints, no loops.

__global__ void __launch_bounds__(256) copy_w_mlp4(const float4* __restrict__ src,
                                                   float4* __restrict__ dst) {
    // thread t in CTA b handles vec4 elements {base+t, +256, +512, +768}
    // where base = b*1024: every warp access is one fully-coalesced 128B
    // line; 524288 vec4 = 512 * 256 * 4 exactly (N=16384, D=128 static),
    // so no bounds checks.
    int base = blockIdx.x * (256 * 4) + threadIdx.x;

    float4 a0 = src[base + 0 * 256];
    float4 a1 = src[base + 1 * 256];
    float4 a2 = src[base + 2 * 256];
    float4 a3 = src[base + 3 * 256];

    dst[base + 0 * 256] = a0;
    dst[base + 1 * 256] = a1;
    dst[base + 2 * 256] = a2;
    dst[base + 3 * 256] = a3;
}

extern "C" void kernel_launch(void* const* d_in, const int* in_sizes, int n_in,
                              void* d_out, int out_size) {
    const float4* W = (const float4*)d_in[0];
    float4* out = (float4*)d_out;
    // out_size = 16384*128 = 2097152 floats = 524288 vec4 -> 512 CTAs exact.
    int blocks = out_size / (4 * 256 * 4);
    copy_w_mlp4<<<blocks, 256>>>(W, out);
}